// round 10
// baseline (speedup 1.0000x reference)
#include <cuda_runtime.h>
#include <cuda_bf16.h>
#include <math.h>
#include <stdint.h>

#define BB 4
#define SS 2048
#define DD 1024
#define DKK 128
#define MTOT (BB * SS)   // 8192

// ---------------------------------------------------------------------------
// Device scratch (allocation-free per harness rules)
// ---------------------------------------------------------------------------
__device__ __nv_bfloat16 g_xh[(size_t)MTOT * DD];
__device__ __nv_bfloat16 g_xl[(size_t)MTOT * DD];
__device__ __nv_bfloat16 g_wqt_h[DKK * DD], g_wqt_l[DKK * DD];
__device__ __nv_bfloat16 g_wkt_h[DKK * DD], g_wkt_l[DKK * DD];
__device__ __nv_bfloat16 g_wvt_h[DD * DD],  g_wvt_l[DD * DD];
__device__ __nv_bfloat16 g_qh[(size_t)MTOT * DKK], g_ql[(size_t)MTOT * DKK];
__device__ __nv_bfloat16 g_kh[(size_t)MTOT * DKK], g_kl[(size_t)MTOT * DKK];
__device__ float g_v[(size_t)MTOT * DD];
__device__ __nv_bfloat16 g_vth[(size_t)BB * DD * SS], g_vtl[(size_t)BB * DD * SS];
__device__ float g_s[(size_t)BB * SS * SS];
__device__ __nv_bfloat16 g_ph[(size_t)BB * SS * SS], g_pl[(size_t)BB * SS * SS];
__device__ float g_xmean[BB * DD];
__device__ float g_vmean[BB * DD];
__device__ int   g_len[BB];

// ---------------------------------------------------------------------------
// mma.sync + cp.async + ldmatrix helpers (plain compute_103-safe PTX)
// ---------------------------------------------------------------------------
__device__ __forceinline__ uint32_t smem_u32(const void* p) {
    uint32_t a;
    asm("{ .reg .u64 t; cvta.to.shared.u64 t, %1; cvt.u32.u64 %0, t; }"
        : "=r"(a) : "l"(p));
    return a;
}
__device__ __forceinline__ void cp_async16(uint32_t dst, const void* src) {
    asm volatile("cp.async.cg.shared.global [%0], [%1], 16;"
                 :: "r"(dst), "l"(src) : "memory");
}
__device__ __forceinline__ void cp_commit() {
    asm volatile("cp.async.commit_group;" ::: "memory");
}
template<int N>
__device__ __forceinline__ void cp_wait() {
    asm volatile("cp.async.wait_group %0;" :: "n"(N) : "memory");
}
__device__ __forceinline__ void mma16816(float* c, const uint32_t* a, const uint32_t* b) {
    asm volatile(
        "mma.sync.aligned.m16n8k16.row.col.f32.bf16.bf16.f32 "
        "{%0,%1,%2,%3}, {%4,%5,%6,%7}, {%8,%9}, {%0,%1,%2,%3};"
        : "+f"(c[0]), "+f"(c[1]), "+f"(c[2]), "+f"(c[3])
        : "r"(a[0]), "r"(a[1]), "r"(a[2]), "r"(a[3]), "r"(b[0]), "r"(b[1]));
}
__device__ __forceinline__ void ldsm_x4(uint32_t* r, uint32_t addr) {
    asm volatile("ldmatrix.sync.aligned.m8n8.x4.shared.b16 {%0,%1,%2,%3}, [%4];"
                 : "=r"(r[0]), "=r"(r[1]), "=r"(r[2]), "=r"(r[3]) : "r"(addr));
}
__device__ __forceinline__ void ldsm_x2(uint32_t* r, uint32_t addr) {
    asm volatile("ldmatrix.sync.aligned.m8n8.x2.shared.b16 {%0,%1}, [%2];"
                 : "=r"(r[0]), "=r"(r[1]) : "r"(addr));
}

__device__ __forceinline__ void split1(float x, __nv_bfloat16& h, __nv_bfloat16& l) {
    h = __float2bfloat16(x);
    l = __float2bfloat16(x - __bfloat162float(h));
}

// ---------------------------------------------------------------------------
// bf16x3 GEMM on HMMA, length-aware tile skipping.  R7-proven mainloop
// (prefetch-before-compute, cp_wait<2>, two barriers per chunk).
// C[M,N] = alpha*(A @ B^T) (+ bias);  A bf16 (hi,lo) [M,K], B bf16 (hi,lo)
// [N,K], both K-major.  CTA tile 128x128, warp tile 64x32, K-chunk 32,
// 3-stage cp.async pipeline.  SMEM row stride 80 B (conflict-free).
//
// LENMODE: 0 none
//          1 projections, batch folded into M (2048 rows/batch):
//              skip tile if (row0 % 2048) >= len[b]
//          2 scores (batch = blockIdx.z): skip if row0 >= len || col0 >= len
//          3 P.V    (batch = blockIdx.z): skip if row0 >= len;
//              Keff = min(causal, round_up(len, 32))
// ---------------------------------------------------------------------------
#define ROWB 80
#define SM_TILE (128 * ROWB)            // 10240
#define STAGE_BYTES (4 * SM_TILE)       // 40960: Ah, Al, Bh, Bl
#define NSTAGE 3
#define SMEM_BYTES (NSTAGE * STAGE_BYTES)  // 122880

template<bool SKIP_UPPER, bool CAUSAL_K, bool BIAS, bool OUT_SPLIT, int LENMODE>
__global__ void __launch_bounds__(256, 1)
gemm_bf16x3(const __nv_bfloat16* __restrict__ Ah, const __nv_bfloat16* __restrict__ Al,
            const __nv_bfloat16* __restrict__ Bh, const __nv_bfloat16* __restrict__ Bl,
            const float* __restrict__ bias, float* __restrict__ C,
            __nv_bfloat16* __restrict__ Ch, __nv_bfloat16* __restrict__ Cl,
            int M, int N, int K,
            long long sA, long long sB, long long sC, float alpha)
{
    if (SKIP_UPPER && blockIdx.x > blockIdx.y) return;

    const int row0 = blockIdx.y * 128;
    const int col0 = blockIdx.x * 128;

    int Keff = K;
    if (CAUSAL_K) { const int kl = (blockIdx.y + 1) * 128; Keff = kl < K ? kl : K; }

    if (LENMODE == 1) {
        const int b = row0 >> 11;                  // 2048 rows per batch
        if ((row0 & 2047) >= g_len[b]) return;
    } else if (LENMODE == 2) {
        const int L = g_len[blockIdx.z];
        if (row0 >= L || col0 >= L) return;
    } else if (LENMODE == 3) {
        const int L = g_len[blockIdx.z];
        if (row0 >= L) return;
        const int kcap = (L + 31) & ~31;
        if (kcap < Keff) Keff = kcap;
    }
    const int nchunk = Keff >> 5;   // K-chunk = 32

    extern __shared__ char smem[];

    const int tid = threadIdx.x;
    const int wid = tid >> 5, lane = tid & 31;
    const int wr = wid >> 2;        // 0..1  warp row (64 rows)
    const int wc = wid & 3;         // 0..3  warp col (32 cols)
    const int r4 = lane >> 2;       // 0..7
    const int c4 = lane & 3;        // 0..3

    Ah += (size_t)blockIdx.z * sA;  Al += (size_t)blockIdx.z * sA;
    Bh += (size_t)blockIdx.z * sB;  Bl += (size_t)blockIdx.z * sB;

    const uint32_t sb = smem_u32(smem);

    // ldmatrix lane geometry
    const int aRowSel = ((lane >> 3) & 1) * 8 + (lane & 7);
    const int aColSel = (lane >> 4) * 16;
    const int bRowSel = lane & 7;
    const int bColSel = ((lane >> 3) & 1) * 16;
    const uint32_t aBase = (uint32_t)((wr * 64 + aRowSel) * ROWB + aColSel);
    const uint32_t bBase = (uint32_t)((wc * 32 + bRowSel) * ROWB + bColSel);

    // loader: per tile, 2 cp.async of 16B per thread (128 rows x 64 B)
    auto ldstage = [&](int c, int s) {
        const long long kofs = (long long)c * 32;
        const uint32_t st = sb + s * STAGE_BYTES;
        const __nv_bfloat16* G[4] = { Ah, Al, Bh, Bl };
        #pragma unroll
        for (int t = 0; t < 4; t++) {
            const int r0 = (t < 2) ? row0 : col0;
            #pragma unroll
            for (int o = 0; o < 2; o++) {
                const int lin = tid + o * 256;
                const int row = lin >> 2;
                const int cb  = (lin & 3) * 16;
                const char* src = (const char*)G[t] + ((size_t)(r0 + row) * K + kofs) * 2 + cb;
                cp_async16(st + t * SM_TILE + row * ROWB + cb, src);
            }
        }
        cp_commit();
    };

    float acc[4][4][4];
    #pragma unroll
    for (int i = 0; i < 4; i++)
        #pragma unroll
        for (int j = 0; j < 4; j++)
            #pragma unroll
            for (int r = 0; r < 4; r++) acc[i][j][r] = 0.0f;

    ldstage(0, 0);
    if (nchunk > 1) ldstage(1, 1); else cp_commit();

    for (int c = 0; c < nchunk; c++) {
        if (c + 2 < nchunk) ldstage(c + 2, (c + 2) % NSTAGE);
        else cp_commit();                 // keep group bookkeeping uniform
        cp_wait<2>();
        __syncthreads();                  // stage c visible

        const uint32_t stg = sb + (c % NSTAGE) * STAGE_BYTES;
        #pragma unroll
        for (int ks = 0; ks < 2; ks++) {
            const uint32_t ko = ks * 32;

            uint32_t ah[4][4], al[4][4], bh[4][2], bl[4][2];
            #pragma unroll
            for (int nt = 0; nt < 4; nt++) {
                const uint32_t off = stg + bBase + nt * (8 * ROWB) + ko;
                ldsm_x2(bh[nt], off + 2 * SM_TILE);
                ldsm_x2(bl[nt], off + 3 * SM_TILE);
            }
            #pragma unroll
            for (int mt = 0; mt < 4; mt++) {
                const uint32_t off = stg + aBase + mt * (16 * ROWB) + ko;
                ldsm_x4(ah[mt], off);
                ldsm_x4(al[mt], off + SM_TILE);
            }

            #pragma unroll
            for (int mt = 0; mt < 4; mt++)
                #pragma unroll
                for (int nt = 0; nt < 4; nt++)
                    mma16816(acc[mt][nt], ah[mt], bh[nt]);
            #pragma unroll
            for (int mt = 0; mt < 4; mt++)
                #pragma unroll
                for (int nt = 0; nt < 4; nt++)
                    mma16816(acc[mt][nt], ah[mt], bl[nt]);
            #pragma unroll
            for (int mt = 0; mt < 4; mt++)
                #pragma unroll
                for (int nt = 0; nt < 4; nt++)
                    mma16816(acc[mt][nt], al[mt], bh[nt]);
        }
        __syncthreads();                  // before buffer reuse
    }

    // epilogue
    #pragma unroll
    for (int mt = 0; mt < 4; mt++) {
        const int r = row0 + wr * 64 + mt * 16 + r4;
        #pragma unroll
        for (int nt = 0; nt < 4; nt++) {
            const int cidx = col0 + wc * 32 + nt * 8 + c4 * 2;
            float b0 = 0.f, b1 = 0.f;
            if (BIAS) { b0 = __ldg(bias + cidx); b1 = __ldg(bias + cidx + 1); }
            const float v00 = alpha * acc[mt][nt][0] + b0;
            const float v01 = alpha * acc[mt][nt][1] + b1;
            const float v10 = alpha * acc[mt][nt][2] + b0;
            const float v11 = alpha * acc[mt][nt][3] + b1;
            if (OUT_SPLIT) {
                __nv_bfloat16 h0, l0, h1, l1;
                split1(v00, h0, l0); split1(v01, h1, l1);
                *(__nv_bfloat162*)(Ch + (size_t)r * N + cidx) = __nv_bfloat162(h0, h1);
                *(__nv_bfloat162*)(Cl + (size_t)r * N + cidx) = __nv_bfloat162(l0, l1);
                split1(v10, h0, l0); split1(v11, h1, l1);
                *(__nv_bfloat162*)(Ch + (size_t)(r + 8) * N + cidx) = __nv_bfloat162(h0, h1);
                *(__nv_bfloat162*)(Cl + (size_t)(r + 8) * N + cidx) = __nv_bfloat162(l0, l1);
            } else {
                float* Cz = C + (size_t)blockIdx.z * sC;
                *(float2*)(Cz + (size_t)r * N + cidx)       = make_float2(v00, v01);
                *(float2*)(Cz + (size_t)(r + 8) * N + cidx) = make_float2(v10, v11);
            }
        }
    }
}

// ---------------------------------------------------------------------------
// per-batch valid length: len[b] = SS - sum(mask[b, :])
// ---------------------------------------------------------------------------
__global__ void compute_len(const int* __restrict__ mask)
{
    const int b = blockIdx.x;
    const int tid = threadIdx.x;
    __shared__ int red[256];
    int s = 0;
    for (int k = tid; k < SS; k += 256) s += mask[b * SS + k];
    red[tid] = s;
    __syncthreads();
    for (int o = 128; o > 0; o >>= 1) {
        if (tid < o) red[tid] += red[tid + o];
        __syncthreads();
    }
    if (tid == 0) g_len[b] = SS - red[0];
}

// ---------------------------------------------------------------------------
// x column mean per batch: g_xmean[b][d] = (1/S) sum_k x[b][k][d]
// ---------------------------------------------------------------------------
__global__ void x_colmean(const float* __restrict__ x)
{
    const int d = blockIdx.x * 256 + threadIdx.x;
    const int b = blockIdx.y;
    const float* xb = x + (size_t)b * SS * DD + d;
    float s = 0.0f;
    for (int k = 0; k < SS; k++) s += xb[(size_t)k * DD];
    g_xmean[b * DD + d] = s * (1.0f / (float)SS);
}

// ---------------------------------------------------------------------------
// vmean[b][d] = xmean[b] . Wv[:,d] + bv[d]   (fp32 GEMV, all batches at once)
// ---------------------------------------------------------------------------
__global__ void vmean_gemv(const float* __restrict__ Wv, const float* __restrict__ bv)
{
    const int d = blockIdx.x * 256 + threadIdx.x;   // 0..1023
    float acc[BB] = {0.f, 0.f, 0.f, 0.f};
    for (int k = 0; k < DD; k++) {
        const float w = __ldg(Wv + (size_t)k * DD + d);
        #pragma unroll
        for (int b = 0; b < BB; b++) acc[b] += g_xmean[b * DD + k] * w;
    }
    const float bvd = __ldg(bv + d);
    #pragma unroll
    for (int b = 0; b < BB; b++) g_vmean[b * DD + d] = acc[b] + bvd;
}

// ---------------------------------------------------------------------------
// fp32 -> bf16 (hi, lo) elementwise split, float4-vectorized
// ---------------------------------------------------------------------------
__global__ void split_fp32(const float* __restrict__ src,
                           __nv_bfloat16* __restrict__ hi, __nv_bfloat16* __restrict__ lo,
                           long long n4)
{
    const long long i = (long long)blockIdx.x * blockDim.x + threadIdx.x;
    if (i >= n4) return;
    float4 v = ((const float4*)src)[i];
    __nv_bfloat16 h0, h1, h2, h3, l0, l1, l2, l3;
    split1(v.x, h0, l0); split1(v.y, h1, l1); split1(v.z, h2, l2); split1(v.w, h3, l3);
    __nv_bfloat162* H = (__nv_bfloat162*)hi;
    __nv_bfloat162* L = (__nv_bfloat162*)lo;
    H[2 * i]     = __nv_bfloat162(h0, h1);
    H[2 * i + 1] = __nv_bfloat162(h2, h3);
    L[2 * i]     = __nv_bfloat162(l0, l1);
    L[2 * i + 1] = __nv_bfloat162(l2, l3);
}

// ---------------------------------------------------------------------------
// fp32 [R,C] -> transposed bf16 hi/lo [C,R], batched; tiled 32x32.
// uselen: skip tiles whose source rows are all >= len[batch].
// ---------------------------------------------------------------------------
__global__ void transpose_split(const float* __restrict__ in,
                                __nv_bfloat16* __restrict__ oh, __nv_bfloat16* __restrict__ ol,
                                int R, int C, long long sIn, long long sOut, int uselen)
{
    const int c0 = blockIdx.x * 32, r0 = blockIdx.y * 32;
    if (uselen && r0 >= g_len[blockIdx.z]) return;
    __shared__ float t[32][33];
    in += (size_t)blockIdx.z * sIn;
    oh += (size_t)blockIdx.z * sOut;
    ol += (size_t)blockIdx.z * sOut;
    const int tx = threadIdx.x & 31, ty = threadIdx.x >> 5;   // 256 thr: ty 0..7
    #pragma unroll
    for (int k = 0; k < 32; k += 8)
        t[ty + k][tx] = in[(size_t)(r0 + ty + k) * C + c0 + tx];
    __syncthreads();
    #pragma unroll
    for (int k = 0; k < 32; k += 8) {
        __nv_bfloat16 h, l;
        split1(t[tx][ty + k], h, l);
        oh[(size_t)(c0 + ty + k) * R + r0 + tx] = h;
        ol[(size_t)(c0 + ty + k) * R + r0 + tx] = l;
    }
}

// ---------------------------------------------------------------------------
// Masked causal softmax: reads fp32 scores, writes bf16 hi/lo P.
// Padded query rows: return (P rows are never written by anyone -> stay zero
// across graph replays; consumed only for out rows that scatter_padded
// overwrites).  Valid rows: work bounded to cap = round_up(len,32); k >= cap
// is never read downstream (P.V truncates K to cap).
// ---------------------------------------------------------------------------
__global__ void masked_softmax(const int* __restrict__ mask)
{
    const int q = blockIdx.x;
    const int b = blockIdx.y;
    if (mask[b * SS + q] != 0) return;

    const size_t off = ((size_t)b * SS + q) * SS;
    const float* row = g_s + off;
    __nv_bfloat16* ph = g_ph + off;
    __nv_bfloat16* pl = g_pl + off;
    const int tid = threadIdx.x;   // 256 threads, 8 elems each

    const int L   = g_len[b];
    const int cap = (L + 31) & ~31;

    __shared__ float red[256];

    float vals[8];
    float m = -INFINITY;
    #pragma unroll
    for (int it = 0; it < 8; it++) {
        const int k = tid + it * 256;
        float s = -INFINITY;
        if (k < cap) {
            const bool valid = (k <= q) && (mask[b * SS + k] == 0);
            s = valid ? row[k] : -INFINITY;
        }
        vals[it] = s;
        m = fmaxf(m, s);
    }
    red[tid] = m;
    __syncthreads();
    for (int o = 128; o > 0; o >>= 1) {
        if (tid < o) red[tid] = fmaxf(red[tid], red[tid + o]);
        __syncthreads();
    }
    m = red[0];
    __syncthreads();

    float sum = 0.0f;
    #pragma unroll
    for (int it = 0; it < 8; it++) {
        const float e = (vals[it] == -INFINITY) ? 0.0f : __expf(vals[it] - m);
        vals[it] = e;
        sum += e;
    }
    red[tid] = sum;
    __syncthreads();
    for (int o = 128; o > 0; o >>= 1) {
        if (tid < o) red[tid] += red[tid + o];
        __syncthreads();
    }
    const float inv = 1.0f / red[0];

    #pragma unroll
    for (int it = 0; it < 8; it++) {
        const int k = tid + it * 256;
        if (k < cap) {
            __nv_bfloat16 h, l;
            split1(vals[it] * inv, h, l);
            ph[k] = h;
            pl[k] = l;
        }
    }
}

// ---------------------------------------------------------------------------
__global__ void scatter_padded(const int* __restrict__ mask, float* __restrict__ out)
{
    const int q = blockIdx.x;
    const int b = blockIdx.y;
    if (mask[b * SS + q] == 0) return;
    const int tid = threadIdx.x;
    float* o = out + ((size_t)b * SS + q) * DD;
    const float* vm = g_vmean + b * DD;
    #pragma unroll
    for (int it = 0; it < 4; it++) o[tid + it * 256] = vm[tid + it * 256];
}

// ---------------------------------------------------------------------------
extern "C" void kernel_launch(void* const* d_in, const int* in_sizes, int n_in,
                              void* d_out, int out_size)
{
    const float* x    = (const float*)d_in[0];
    const int*   mask = (const int*)d_in[1];
    const float* Wq   = (const float*)d_in[2];
    const float* bq   = (const float*)d_in[3];
    const float* Wk   = (const float*)d_in[4];
    const float* bk   = (const float*)d_in[5];
    const float* Wv   = (const float*)d_in[6];
    const float* bv   = (const float*)d_in[7];
    float* out = (float*)d_out;

    cudaFuncSetAttribute(gemm_bf16x3<false, false, true, true, 1>,
                         cudaFuncAttributeMaxDynamicSharedMemorySize, SMEM_BYTES);
    cudaFuncSetAttribute(gemm_bf16x3<false, false, true, false, 1>,
                         cudaFuncAttributeMaxDynamicSharedMemorySize, SMEM_BYTES);
    cudaFuncSetAttribute(gemm_bf16x3<true, false, false, false, 2>,
                         cudaFuncAttributeMaxDynamicSharedMemorySize, SMEM_BYTES);
    cudaFuncSetAttribute(gemm_bf16x3<false, true, false, false, 3>,
                         cudaFuncAttributeMaxDynamicSharedMemorySize, SMEM_BYTES);

    __nv_bfloat16 *xh, *xl, *wqth, *wqtl, *wkth, *wktl, *wvth, *wvtl;
    __nv_bfloat16 *qh, *ql, *kh, *kl, *vth, *vtl, *ph, *pl;
    float *v, *s;
    cudaGetSymbolAddress((void**)&xh, g_xh);     cudaGetSymbolAddress((void**)&xl, g_xl);
    cudaGetSymbolAddress((void**)&wqth, g_wqt_h); cudaGetSymbolAddress((void**)&wqtl, g_wqt_l);
    cudaGetSymbolAddress((void**)&wkth, g_wkt_h); cudaGetSymbolAddress((void**)&wktl, g_wkt_l);
    cudaGetSymbolAddress((void**)&wvth, g_wvt_h); cudaGetSymbolAddress((void**)&wvtl, g_wvt_l);
    cudaGetSymbolAddress((void**)&qh, g_qh);     cudaGetSymbolAddress((void**)&ql, g_ql);
    cudaGetSymbolAddress((void**)&kh, g_kh);     cudaGetSymbolAddress((void**)&kl, g_kl);
    cudaGetSymbolAddress((void**)&v, g_v);
    cudaGetSymbolAddress((void**)&vth, g_vth);   cudaGetSymbolAddress((void**)&vtl, g_vtl);
    cudaGetSymbolAddress((void**)&s, g_s);
    cudaGetSymbolAddress((void**)&ph, g_ph);     cudaGetSymbolAddress((void**)&pl, g_pl);

    const float scale = 1.0f / sqrtf((float)DKK);

    // 0. per-batch lengths; x column means; vmean = xmean @ Wv + bv
    compute_len<<<BB, 256>>>(mask);
    x_colmean<<<dim3(DD / 256, BB), 256>>>(x);
    vmean_gemv<<<DD / 256, 256>>>(Wv, bv);

    // 1. split x into bf16 hi/lo
    {
        long long n4 = (long long)MTOT * DD / 4;
        split_fp32<<<(unsigned)((n4 + 255) / 256), 256>>>(x, xh, xl, n4);
    }
    // 2. transpose + split weights:  W[K,N] -> WT[N,K]
    transpose_split<<<dim3(DKK / 32, DD / 32, 1), 256>>>(Wq, wqth, wqtl, DD, DKK, 0, 0, 0);
    transpose_split<<<dim3(DKK / 32, DD / 32, 1), 256>>>(Wk, wkth, wktl, DD, DKK, 0, 0, 0);
    transpose_split<<<dim3(DD / 32, DD / 32, 1), 256>>>(Wv, wvth, wvtl, DD, DD, 0, 0, 0);

    // 3. projections: q, k, v all skip rows >= len
    gemm_bf16x3<false, false, true, true, 1><<<dim3(1, MTOT / 128, 1), 256, SMEM_BYTES>>>(
        xh, xl, wqth, wqtl, bq, nullptr, qh, ql, MTOT, DKK, DD, 0, 0, 0, 1.0f);
    gemm_bf16x3<false, false, true, true, 1><<<dim3(1, MTOT / 128, 1), 256, SMEM_BYTES>>>(
        xh, xl, wkth, wktl, bk, nullptr, kh, kl, MTOT, DKK, DD, 0, 0, 0, 1.0f);
    gemm_bf16x3<false, false, true, false, 1><<<dim3(DD / 128, MTOT / 128, 1), 256, SMEM_BYTES>>>(
        xh, xl, wvth, wvtl, bv, v, nullptr, nullptr, MTOT, DD, DD, 0, 0, 0, 1.0f);

    // 4. transpose+split v per batch (skip rows >= len; those stay zero)
    transpose_split<<<dim3(DD / 32, SS / 32, BB), 256>>>(
        v, vth, vtl, SS, DD, (long long)SS * DD, (long long)SS * DD, 1);

    // 5. scores: lower-triangle tiles, both dims clipped to len
    gemm_bf16x3<true, false, false, false, 2><<<dim3(SS / 128, SS / 128, BB), 256, SMEM_BYTES>>>(
        qh, ql, kh, kl, nullptr, s, nullptr, nullptr, SS, SS, DKK,
        (long long)SS * DKK, (long long)SS * DKK, (long long)SS * SS, scale);

    // 6. masked softmax -> P (bf16 hi/lo), bounded to round_up(len,32)
    masked_softmax<<<dim3(SS, BB), 256>>>(mask);

    // 7. out = P @ V^T-layout, K truncated to min(causal, len); skip rows>=len
    gemm_bf16x3<false, true, false, false, 3><<<dim3(DD / 128, SS / 128, BB), 256, SMEM_BYTES>>>(
        ph, pl, vth, vtl, nullptr, out, nullptr, nullptr, SS, DD, SS,
        (long long)SS * SS, (long long)DD * SS, (long long)SS * DD, 1.0f);

    // 8. padded rows <- uniform attention (vmean from xmean @ Wv + bv)
    scatter_padded<<<dim3(SS, BB), 256>>>(mask, out);
}

// round 11
// speedup vs baseline: 1.3600x; 1.3600x over previous
#include <cuda_runtime.h>
#include <cuda_bf16.h>
#include <math.h>
#include <stdint.h>

#define BB 4
#define SS 2048
#define DD 1024
#define DKK 128
#define MTOT (BB * SS)   // 8192
#define KSLICE 16

// ---------------------------------------------------------------------------
// Device scratch (allocation-free per harness rules)
// ---------------------------------------------------------------------------
__device__ __nv_bfloat16 g_xh[(size_t)MTOT * DD];
__device__ __nv_bfloat16 g_xl[(size_t)MTOT * DD];
__device__ __nv_bfloat16 g_wqt_h[DKK * DD], g_wqt_l[DKK * DD];
__device__ __nv_bfloat16 g_wkt_h[DKK * DD], g_wkt_l[DKK * DD];
__device__ __nv_bfloat16 g_wvt_h[DD * DD],  g_wvt_l[DD * DD];
__device__ __nv_bfloat16 g_qh[(size_t)MTOT * DKK], g_ql[(size_t)MTOT * DKK];
__device__ __nv_bfloat16 g_kh[(size_t)MTOT * DKK], g_kl[(size_t)MTOT * DKK];
__device__ float g_v[(size_t)MTOT * DD];
__device__ __nv_bfloat16 g_vth[(size_t)BB * DD * SS], g_vtl[(size_t)BB * DD * SS];
__device__ float g_s[(size_t)BB * SS * SS];
__device__ __nv_bfloat16 g_ph[(size_t)BB * SS * SS], g_pl[(size_t)BB * SS * SS];
__device__ float g_xpart[KSLICE][BB][DD];
__device__ float g_vpart[KSLICE][BB][DD];
__device__ float g_xmean[BB * DD];
__device__ float g_vmean[BB * DD];
__device__ int   g_len[BB];

// ---------------------------------------------------------------------------
// mma.sync + cp.async + ldmatrix helpers (plain compute_103-safe PTX)
// ---------------------------------------------------------------------------
__device__ __forceinline__ uint32_t smem_u32(const void* p) {
    uint32_t a;
    asm("{ .reg .u64 t; cvta.to.shared.u64 t, %1; cvt.u32.u64 %0, t; }"
        : "=r"(a) : "l"(p));
    return a;
}
__device__ __forceinline__ void cp_async16(uint32_t dst, const void* src) {
    asm volatile("cp.async.cg.shared.global [%0], [%1], 16;"
                 :: "r"(dst), "l"(src) : "memory");
}
__device__ __forceinline__ void cp_commit() {
    asm volatile("cp.async.commit_group;" ::: "memory");
}
template<int N>
__device__ __forceinline__ void cp_wait() {
    asm volatile("cp.async.wait_group %0;" :: "n"(N) : "memory");
}
__device__ __forceinline__ void mma16816(float* c, const uint32_t* a, const uint32_t* b) {
    asm volatile(
        "mma.sync.aligned.m16n8k16.row.col.f32.bf16.bf16.f32 "
        "{%0,%1,%2,%3}, {%4,%5,%6,%7}, {%8,%9}, {%0,%1,%2,%3};"
        : "+f"(c[0]), "+f"(c[1]), "+f"(c[2]), "+f"(c[3])
        : "r"(a[0]), "r"(a[1]), "r"(a[2]), "r"(a[3]), "r"(b[0]), "r"(b[1]));
}
__device__ __forceinline__ void ldsm_x4(uint32_t* r, uint32_t addr) {
    asm volatile("ldmatrix.sync.aligned.m8n8.x4.shared.b16 {%0,%1,%2,%3}, [%4];"
                 : "=r"(r[0]), "=r"(r[1]), "=r"(r[2]), "=r"(r[3]) : "r"(addr));
}
__device__ __forceinline__ void ldsm_x2(uint32_t* r, uint32_t addr) {
    asm volatile("ldmatrix.sync.aligned.m8n8.x2.shared.b16 {%0,%1}, [%2];"
                 : "=r"(r[0]), "=r"(r[1]) : "r"(addr));
}

__device__ __forceinline__ void split1(float x, __nv_bfloat16& h, __nv_bfloat16& l) {
    h = __float2bfloat16(x);
    l = __float2bfloat16(x - __bfloat162float(h));
}

// ---------------------------------------------------------------------------
// bf16x3 GEMM on HMMA, length-aware tile skipping.  R7-proven mainloop.
// LENMODE: 0 none; 1 proj (skip (row0%2048)>=len); 2 scores; 3 P.V
// ---------------------------------------------------------------------------
#define ROWB 80
#define SM_TILE (128 * ROWB)            // 10240
#define STAGE_BYTES (4 * SM_TILE)       // 40960: Ah, Al, Bh, Bl
#define NSTAGE 3
#define SMEM_BYTES (NSTAGE * STAGE_BYTES)  // 122880

template<bool SKIP_UPPER, bool CAUSAL_K, bool BIAS, bool OUT_SPLIT, int LENMODE>
__global__ void __launch_bounds__(256, 1)
gemm_bf16x3(const __nv_bfloat16* __restrict__ Ah, const __nv_bfloat16* __restrict__ Al,
            const __nv_bfloat16* __restrict__ Bh, const __nv_bfloat16* __restrict__ Bl,
            const float* __restrict__ bias, float* __restrict__ C,
            __nv_bfloat16* __restrict__ Ch, __nv_bfloat16* __restrict__ Cl,
            int M, int N, int K,
            long long sA, long long sB, long long sC, float alpha)
{
    if (SKIP_UPPER && blockIdx.x > blockIdx.y) return;

    const int row0 = blockIdx.y * 128;
    const int col0 = blockIdx.x * 128;

    int Keff = K;
    if (CAUSAL_K) { const int kl = (blockIdx.y + 1) * 128; Keff = kl < K ? kl : K; }

    if (LENMODE == 1) {
        const int b = row0 >> 11;
        if ((row0 & 2047) >= g_len[b]) return;
    } else if (LENMODE == 2) {
        const int L = g_len[blockIdx.z];
        if (row0 >= L || col0 >= L) return;
    } else if (LENMODE == 3) {
        const int L = g_len[blockIdx.z];
        if (row0 >= L) return;
        const int kcap = (L + 31) & ~31;
        if (kcap < Keff) Keff = kcap;
    }
    const int nchunk = Keff >> 5;   // K-chunk = 32

    extern __shared__ char smem[];

    const int tid = threadIdx.x;
    const int wid = tid >> 5, lane = tid & 31;
    const int wr = wid >> 2;
    const int wc = wid & 3;
    const int r4 = lane >> 2;
    const int c4 = lane & 3;

    Ah += (size_t)blockIdx.z * sA;  Al += (size_t)blockIdx.z * sA;
    Bh += (size_t)blockIdx.z * sB;  Bl += (size_t)blockIdx.z * sB;

    const uint32_t sb = smem_u32(smem);

    const int aRowSel = ((lane >> 3) & 1) * 8 + (lane & 7);
    const int aColSel = (lane >> 4) * 16;
    const int bRowSel = lane & 7;
    const int bColSel = ((lane >> 3) & 1) * 16;
    const uint32_t aBase = (uint32_t)((wr * 64 + aRowSel) * ROWB + aColSel);
    const uint32_t bBase = (uint32_t)((wc * 32 + bRowSel) * ROWB + bColSel);

    auto ldstage = [&](int c, int s) {
        const long long kofs = (long long)c * 32;
        const uint32_t st = sb + s * STAGE_BYTES;
        const __nv_bfloat16* G[4] = { Ah, Al, Bh, Bl };
        #pragma unroll
        for (int t = 0; t < 4; t++) {
            const int r0 = (t < 2) ? row0 : col0;
            #pragma unroll
            for (int o = 0; o < 2; o++) {
                const int lin = tid + o * 256;
                const int row = lin >> 2;
                const int cb  = (lin & 3) * 16;
                const char* src = (const char*)G[t] + ((size_t)(r0 + row) * K + kofs) * 2 + cb;
                cp_async16(st + t * SM_TILE + row * ROWB + cb, src);
            }
        }
        cp_commit();
    };

    float acc[4][4][4];
    #pragma unroll
    for (int i = 0; i < 4; i++)
        #pragma unroll
        for (int j = 0; j < 4; j++)
            #pragma unroll
            for (int r = 0; r < 4; r++) acc[i][j][r] = 0.0f;

    ldstage(0, 0);
    if (nchunk > 1) ldstage(1, 1); else cp_commit();

    for (int c = 0; c < nchunk; c++) {
        if (c + 2 < nchunk) ldstage(c + 2, (c + 2) % NSTAGE);
        else cp_commit();
        cp_wait<2>();
        __syncthreads();

        const uint32_t stg = sb + (c % NSTAGE) * STAGE_BYTES;
        #pragma unroll
        for (int ks = 0; ks < 2; ks++) {
            const uint32_t ko = ks * 32;

            uint32_t ah[4][4], al[4][4], bh[4][2], bl[4][2];
            #pragma unroll
            for (int nt = 0; nt < 4; nt++) {
                const uint32_t off = stg + bBase + nt * (8 * ROWB) + ko;
                ldsm_x2(bh[nt], off + 2 * SM_TILE);
                ldsm_x2(bl[nt], off + 3 * SM_TILE);
            }
            #pragma unroll
            for (int mt = 0; mt < 4; mt++) {
                const uint32_t off = stg + aBase + mt * (16 * ROWB) + ko;
                ldsm_x4(ah[mt], off);
                ldsm_x4(al[mt], off + SM_TILE);
            }

            #pragma unroll
            for (int mt = 0; mt < 4; mt++)
                #pragma unroll
                for (int nt = 0; nt < 4; nt++)
                    mma16816(acc[mt][nt], ah[mt], bh[nt]);
            #pragma unroll
            for (int mt = 0; mt < 4; mt++)
                #pragma unroll
                for (int nt = 0; nt < 4; nt++)
                    mma16816(acc[mt][nt], ah[mt], bl[nt]);
            #pragma unroll
            for (int mt = 0; mt < 4; mt++)
                #pragma unroll
                for (int nt = 0; nt < 4; nt++)
                    mma16816(acc[mt][nt], al[mt], bh[nt]);
        }
        __syncthreads();
    }

    // epilogue
    #pragma unroll
    for (int mt = 0; mt < 4; mt++) {
        const int r = row0 + wr * 64 + mt * 16 + r4;
        #pragma unroll
        for (int nt = 0; nt < 4; nt++) {
            const int cidx = col0 + wc * 32 + nt * 8 + c4 * 2;
            float b0 = 0.f, b1 = 0.f;
            if (BIAS) { b0 = __ldg(bias + cidx); b1 = __ldg(bias + cidx + 1); }
            const float v00 = alpha * acc[mt][nt][0] + b0;
            const float v01 = alpha * acc[mt][nt][1] + b1;
            const float v10 = alpha * acc[mt][nt][2] + b0;
            const float v11 = alpha * acc[mt][nt][3] + b1;
            if (OUT_SPLIT) {
                __nv_bfloat16 h0, l0, h1, l1;
                split1(v00, h0, l0); split1(v01, h1, l1);
                *(__nv_bfloat162*)(Ch + (size_t)r * N + cidx) = __nv_bfloat162(h0, h1);
                *(__nv_bfloat162*)(Cl + (size_t)r * N + cidx) = __nv_bfloat162(l0, l1);
                split1(v10, h0, l0); split1(v11, h1, l1);
                *(__nv_bfloat162*)(Ch + (size_t)(r + 8) * N + cidx) = __nv_bfloat162(h0, h1);
                *(__nv_bfloat162*)(Cl + (size_t)(r + 8) * N + cidx) = __nv_bfloat162(l0, l1);
            } else {
                float* Cz = C + (size_t)blockIdx.z * sC;
                *(float2*)(Cz + (size_t)r * N + cidx)       = make_float2(v00, v01);
                *(float2*)(Cz + (size_t)(r + 8) * N + cidx) = make_float2(v10, v11);
            }
        }
    }
}

// ---------------------------------------------------------------------------
// per-batch valid length: len[b] = SS - sum(mask[b, :])
// ---------------------------------------------------------------------------
__global__ void compute_len(const int* __restrict__ mask)
{
    const int b = blockIdx.x;
    const int tid = threadIdx.x;
    __shared__ int red[256];
    int s = 0;
    for (int k = tid; k < SS; k += 256) s += mask[b * SS + k];
    red[tid] = s;
    __syncthreads();
    for (int o = 128; o > 0; o >>= 1) {
        if (tid < o) red[tid] += red[tid + o];
        __syncthreads();
    }
    if (tid == 0) g_len[b] = SS - red[0];
}

// ---------------------------------------------------------------------------
// x column mean, two-stage for parallelism.
// Stage 1: 256 CTAs, each sums a 128-row slice: g_xpart[slice][b][d].
// Stage 2: 16 CTAs reduce the 16 partials -> g_xmean.
// ---------------------------------------------------------------------------
__global__ void x_colmean_part(const float* __restrict__ x)
{
    const int d = blockIdx.x * 256 + threadIdx.x;
    const int b = blockIdx.y;
    const int sl = blockIdx.z;
    const float* xb = x + (size_t)b * SS * DD + (size_t)sl * 128 * DD + d;
    float s = 0.0f;
    #pragma unroll 8
    for (int k = 0; k < 128; k++) s += xb[(size_t)k * DD];
    g_xpart[sl][b][d] = s;
}
__global__ void x_colmean_finish()
{
    const int d = blockIdx.x * 256 + threadIdx.x;
    const int b = blockIdx.y;
    float s = 0.0f;
    #pragma unroll
    for (int sl = 0; sl < KSLICE; sl++) s += g_xpart[sl][b][d];
    g_xmean[b * DD + d] = s * (1.0f / (float)SS);
}

// ---------------------------------------------------------------------------
// vmean = xmean @ Wv + bv, two-stage.
// Stage 1: 64 CTAs, each a 64-row k-slice of Wv: g_vpart[slice][b][d].
// Stage 2: reduce + bias -> g_vmean.
// ---------------------------------------------------------------------------
__global__ void vmean_part(const float* __restrict__ Wv)
{
    const int d = blockIdx.x * 256 + threadIdx.x;   // 0..1023
    const int sl = blockIdx.y;                      // 0..15
    float acc[BB] = {0.f, 0.f, 0.f, 0.f};
    #pragma unroll 4
    for (int kk = 0; kk < 64; kk++) {
        const int k = sl * 64 + kk;
        const float w = __ldg(Wv + (size_t)k * DD + d);
        #pragma unroll
        for (int b = 0; b < BB; b++) acc[b] += g_xmean[b * DD + k] * w;
    }
    #pragma unroll
    for (int b = 0; b < BB; b++) g_vpart[sl][b][d] = acc[b];
}
__global__ void vmean_finish(const float* __restrict__ bv)
{
    const int d = blockIdx.x * 256 + threadIdx.x;
    const int b = blockIdx.y;
    float s = __ldg(bv + d);
    #pragma unroll
    for (int sl = 0; sl < KSLICE; sl++) s += g_vpart[sl][b][d];
    g_vmean[b * DD + d] = s;
}

// ---------------------------------------------------------------------------
// fp32 -> bf16 (hi, lo) elementwise split, float4-vectorized
// ---------------------------------------------------------------------------
__global__ void split_fp32(const float* __restrict__ src,
                           __nv_bfloat16* __restrict__ hi, __nv_bfloat16* __restrict__ lo,
                           long long n4)
{
    const long long i = (long long)blockIdx.x * blockDim.x + threadIdx.x;
    if (i >= n4) return;
    float4 v = ((const float4*)src)[i];
    __nv_bfloat16 h0, h1, h2, h3, l0, l1, l2, l3;
    split1(v.x, h0, l0); split1(v.y, h1, l1); split1(v.z, h2, l2); split1(v.w, h3, l3);
    __nv_bfloat162* H = (__nv_bfloat162*)hi;
    __nv_bfloat162* L = (__nv_bfloat162*)lo;
    H[2 * i]     = __nv_bfloat162(h0, h1);
    H[2 * i + 1] = __nv_bfloat162(h2, h3);
    L[2 * i]     = __nv_bfloat162(l0, l1);
    L[2 * i + 1] = __nv_bfloat162(l2, l3);
}

// ---------------------------------------------------------------------------
// fp32 [R,C] -> transposed bf16 hi/lo [C,R], batched; tiled 32x32.
// uselen: skip tiles whose source rows are all >= len[batch].
// ---------------------------------------------------------------------------
__global__ void transpose_split(const float* __restrict__ in,
                                __nv_bfloat16* __restrict__ oh, __nv_bfloat16* __restrict__ ol,
                                int R, int C, long long sIn, long long sOut, int uselen)
{
    const int c0 = blockIdx.x * 32, r0 = blockIdx.y * 32;
    if (uselen && r0 >= g_len[blockIdx.z]) return;
    __shared__ float t[32][33];
    in += (size_t)blockIdx.z * sIn;
    oh += (size_t)blockIdx.z * sOut;
    ol += (size_t)blockIdx.z * sOut;
    const int tx = threadIdx.x & 31, ty = threadIdx.x >> 5;
    #pragma unroll
    for (int k = 0; k < 32; k += 8)
        t[ty + k][tx] = in[(size_t)(r0 + ty + k) * C + c0 + tx];
    __syncthreads();
    #pragma unroll
    for (int k = 0; k < 32; k += 8) {
        __nv_bfloat16 h, l;
        split1(t[tx][ty + k], h, l);
        oh[(size_t)(c0 + ty + k) * R + r0 + tx] = h;
        ol[(size_t)(c0 + ty + k) * R + r0 + tx] = l;
    }
}

// ---------------------------------------------------------------------------
// Masked causal softmax: reads fp32 scores, writes bf16 hi/lo P.
// Padded query rows: return (P rows stay zero; out rows overwritten later).
// Valid rows: bounded to cap = round_up(len,32).
// ---------------------------------------------------------------------------
__global__ void masked_softmax(const int* __restrict__ mask)
{
    const int q = blockIdx.x;
    const int b = blockIdx.y;
    if (mask[b * SS + q] != 0) return;

    const size_t off = ((size_t)b * SS + q) * SS;
    const float* row = g_s + off;
    __nv_bfloat16* ph = g_ph + off;
    __nv_bfloat16* pl = g_pl + off;
    const int tid = threadIdx.x;

    const int L   = g_len[b];
    const int cap = (L + 31) & ~31;

    __shared__ float red[256];

    float vals[8];
    float m = -INFINITY;
    #pragma unroll
    for (int it = 0; it < 8; it++) {
        const int k = tid + it * 256;
        float s = -INFINITY;
        if (k < cap) {
            const bool valid = (k <= q) && (mask[b * SS + k] == 0);
            s = valid ? row[k] : -INFINITY;
        }
        vals[it] = s;
        m = fmaxf(m, s);
    }
    red[tid] = m;
    __syncthreads();
    for (int o = 128; o > 0; o >>= 1) {
        if (tid < o) red[tid] = fmaxf(red[tid], red[tid + o]);
        __syncthreads();
    }
    m = red[0];
    __syncthreads();

    float sum = 0.0f;
    #pragma unroll
    for (int it = 0; it < 8; it++) {
        const float e = (vals[it] == -INFINITY) ? 0.0f : __expf(vals[it] - m);
        vals[it] = e;
        sum += e;
    }
    red[tid] = sum;
    __syncthreads();
    for (int o = 128; o > 0; o >>= 1) {
        if (tid < o) red[tid] += red[tid + o];
        __syncthreads();
    }
    const float inv = 1.0f / red[0];

    #pragma unroll
    for (int it = 0; it < 8; it++) {
        const int k = tid + it * 256;
        if (k < cap) {
            __nv_bfloat16 h, l;
            split1(vals[it] * inv, h, l);
            ph[k] = h;
            pl[k] = l;
        }
    }
}

// ---------------------------------------------------------------------------
__global__ void scatter_padded(const int* __restrict__ mask, float* __restrict__ out)
{
    const int q = blockIdx.x;
    const int b = blockIdx.y;
    if (mask[b * SS + q] == 0) return;
    const int tid = threadIdx.x;
    float* o = out + ((size_t)b * SS + q) * DD;
    const float* vm = g_vmean + b * DD;
    #pragma unroll
    for (int it = 0; it < 4; it++) o[tid + it * 256] = vm[tid + it * 256];
}

// ---------------------------------------------------------------------------
extern "C" void kernel_launch(void* const* d_in, const int* in_sizes, int n_in,
                              void* d_out, int out_size)
{
    const float* x    = (const float*)d_in[0];
    const int*   mask = (const int*)d_in[1];
    const float* Wq   = (const float*)d_in[2];
    const float* bq   = (const float*)d_in[3];
    const float* Wk   = (const float*)d_in[4];
    const float* bk   = (const float*)d_in[5];
    const float* Wv   = (const float*)d_in[6];
    const float* bv   = (const float*)d_in[7];
    float* out = (float*)d_out;

    cudaFuncSetAttribute(gemm_bf16x3<false, false, true, true, 1>,
                         cudaFuncAttributeMaxDynamicSharedMemorySize, SMEM_BYTES);
    cudaFuncSetAttribute(gemm_bf16x3<false, false, true, false, 1>,
                         cudaFuncAttributeMaxDynamicSharedMemorySize, SMEM_BYTES);
    cudaFuncSetAttribute(gemm_bf16x3<true, false, false, false, 2>,
                         cudaFuncAttributeMaxDynamicSharedMemorySize, SMEM_BYTES);
    cudaFuncSetAttribute(gemm_bf16x3<false, true, false, false, 3>,
                         cudaFuncAttributeMaxDynamicSharedMemorySize, SMEM_BYTES);

    __nv_bfloat16 *xh, *xl, *wqth, *wqtl, *wkth, *wktl, *wvth, *wvtl;
    __nv_bfloat16 *qh, *ql, *kh, *kl, *vth, *vtl, *ph, *pl;
    float *v, *s;
    cudaGetSymbolAddress((void**)&xh, g_xh);     cudaGetSymbolAddress((void**)&xl, g_xl);
    cudaGetSymbolAddress((void**)&wqth, g_wqt_h); cudaGetSymbolAddress((void**)&wqtl, g_wqt_l);
    cudaGetSymbolAddress((void**)&wkth, g_wkt_h); cudaGetSymbolAddress((void**)&wktl, g_wkt_l);
    cudaGetSymbolAddress((void**)&wvth, g_wvt_h); cudaGetSymbolAddress((void**)&wvtl, g_wvt_l);
    cudaGetSymbolAddress((void**)&qh, g_qh);     cudaGetSymbolAddress((void**)&ql, g_ql);
    cudaGetSymbolAddress((void**)&kh, g_kh);     cudaGetSymbolAddress((void**)&kl, g_kl);
    cudaGetSymbolAddress((void**)&v, g_v);
    cudaGetSymbolAddress((void**)&vth, g_vth);   cudaGetSymbolAddress((void**)&vtl, g_vtl);
    cudaGetSymbolAddress((void**)&s, g_s);
    cudaGetSymbolAddress((void**)&ph, g_ph);     cudaGetSymbolAddress((void**)&pl, g_pl);

    const float scale = 1.0f / sqrtf((float)DKK);

    // 0. per-batch lengths; xmean (2-stage); vmean = xmean @ Wv + bv (2-stage)
    compute_len<<<BB, 256>>>(mask);
    x_colmean_part<<<dim3(DD / 256, BB, KSLICE), 256>>>(x);
    x_colmean_finish<<<dim3(DD / 256, BB), 256>>>();
    vmean_part<<<dim3(DD / 256, KSLICE), 256>>>(Wv);
    vmean_finish<<<dim3(DD / 256, BB), 256>>>(bv);

    // 1. split x into bf16 hi/lo
    {
        long long n4 = (long long)MTOT * DD / 4;
        split_fp32<<<(unsigned)((n4 + 255) / 256), 256>>>(x, xh, xl, n4);
    }
    // 2. transpose + split weights:  W[K,N] -> WT[N,K]
    transpose_split<<<dim3(DKK / 32, DD / 32, 1), 256>>>(Wq, wqth, wqtl, DD, DKK, 0, 0, 0);
    transpose_split<<<dim3(DKK / 32, DD / 32, 1), 256>>>(Wk, wkth, wktl, DD, DKK, 0, 0, 0);
    transpose_split<<<dim3(DD / 32, DD / 32, 1), 256>>>(Wv, wvth, wvtl, DD, DD, 0, 0, 0);

    // 3. projections: q, k, v all skip rows >= len
    gemm_bf16x3<false, false, true, true, 1><<<dim3(1, MTOT / 128, 1), 256, SMEM_BYTES>>>(
        xh, xl, wqth, wqtl, bq, nullptr, qh, ql, MTOT, DKK, DD, 0, 0, 0, 1.0f);
    gemm_bf16x3<false, false, true, true, 1><<<dim3(1, MTOT / 128, 1), 256, SMEM_BYTES>>>(
        xh, xl, wkth, wktl, bk, nullptr, kh, kl, MTOT, DKK, DD, 0, 0, 0, 1.0f);
    gemm_bf16x3<false, false, true, false, 1><<<dim3(DD / 128, MTOT / 128, 1), 256, SMEM_BYTES>>>(
        xh, xl, wvth, wvtl, bv, v, nullptr, nullptr, MTOT, DD, DD, 0, 0, 0, 1.0f);

    // 4. transpose+split v per batch (skip rows >= len; those stay zero)
    transpose_split<<<dim3(DD / 32, SS / 32, BB), 256>>>(
        v, vth, vtl, SS, DD, (long long)SS * DD, (long long)SS * DD, 1);

    // 5. scores: lower-triangle tiles, both dims clipped to len
    gemm_bf16x3<true, false, false, false, 2><<<dim3(SS / 128, SS / 128, BB), 256, SMEM_BYTES>>>(
        qh, ql, kh, kl, nullptr, s, nullptr, nullptr, SS, SS, DKK,
        (long long)SS * DKK, (long long)SS * DKK, (long long)SS * SS, scale);

    // 6. masked softmax -> P (bf16 hi/lo), bounded to round_up(len,32)
    masked_softmax<<<dim3(SS, BB), 256>>>(mask);

    // 7. out = P @ V^T-layout, K truncated to min(causal, len); skip rows>=len
    gemm_bf16x3<false, true, false, false, 3><<<dim3(DD / 128, SS / 128, BB), 256, SMEM_BYTES>>>(
        ph, pl, vth, vtl, nullptr, out, nullptr, nullptr, SS, DD, SS,
        (long long)SS * SS, (long long)DD * SS, (long long)SS * DD, 1.0f);

    // 8. padded rows <- uniform attention (vmean from xmean @ Wv + bv)
    scatter_padded<<<dim3(SS, BB), 256>>>(mask, out);
}

// round 12
// speedup vs baseline: 1.5116x; 1.1115x over previous
#include <cuda_runtime.h>
#include <cuda_bf16.h>
#include <math.h>
#include <stdint.h>

#define BB 4
#define SS 2048
#define DD 1024
#define DKK 128
#define MTOT (BB * SS)   // 8192
#define KSLICE 16
#define VSLICE 64

// ---------------------------------------------------------------------------
// Device scratch (allocation-free per harness rules)
// ---------------------------------------------------------------------------
__device__ __nv_bfloat16 g_xh[(size_t)MTOT * DD];
__device__ __nv_bfloat16 g_xl[(size_t)MTOT * DD];
__device__ __nv_bfloat16 g_wqkt_h[2 * DKK * DD], g_wqkt_l[2 * DKK * DD]; // [256,1024]
__device__ __nv_bfloat16 g_wvt_h[DD * DD],  g_wvt_l[DD * DD];
__device__ float g_bqk[2 * DKK];
__device__ __nv_bfloat16 g_qkh[(size_t)MTOT * 2 * DKK], g_qkl[(size_t)MTOT * 2 * DKK];
__device__ float g_v[(size_t)MTOT * DD];
__device__ __nv_bfloat16 g_vth[(size_t)BB * DD * SS], g_vtl[(size_t)BB * DD * SS];
__device__ float g_s[(size_t)BB * SS * SS];
__device__ __nv_bfloat16 g_ph[(size_t)BB * SS * SS], g_pl[(size_t)BB * SS * SS];
__device__ float g_xpart[KSLICE][BB][DD];
__device__ float g_vpart[VSLICE][BB][DD];
__device__ float g_xmean[BB * DD];
__device__ float g_vmean[BB * DD];
__device__ int   g_len[BB];

// ---------------------------------------------------------------------------
// mma.sync + cp.async + ldmatrix helpers (plain compute_103-safe PTX)
// ---------------------------------------------------------------------------
__device__ __forceinline__ uint32_t smem_u32(const void* p) {
    uint32_t a;
    asm("{ .reg .u64 t; cvta.to.shared.u64 t, %1; cvt.u32.u64 %0, t; }"
        : "=r"(a) : "l"(p));
    return a;
}
__device__ __forceinline__ void cp_async16(uint32_t dst, const void* src) {
    asm volatile("cp.async.cg.shared.global [%0], [%1], 16;"
                 :: "r"(dst), "l"(src) : "memory");
}
__device__ __forceinline__ void cp_commit() {
    asm volatile("cp.async.commit_group;" ::: "memory");
}
template<int N>
__device__ __forceinline__ void cp_wait() {
    asm volatile("cp.async.wait_group %0;" :: "n"(N) : "memory");
}
__device__ __forceinline__ void mma16816(float* c, const uint32_t* a, const uint32_t* b) {
    asm volatile(
        "mma.sync.aligned.m16n8k16.row.col.f32.bf16.bf16.f32 "
        "{%0,%1,%2,%3}, {%4,%5,%6,%7}, {%8,%9}, {%0,%1,%2,%3};"
        : "+f"(c[0]), "+f"(c[1]), "+f"(c[2]), "+f"(c[3])
        : "r"(a[0]), "r"(a[1]), "r"(a[2]), "r"(a[3]), "r"(b[0]), "r"(b[1]));
}
__device__ __forceinline__ void ldsm_x4(uint32_t* r, uint32_t addr) {
    asm volatile("ldmatrix.sync.aligned.m8n8.x4.shared.b16 {%0,%1,%2,%3}, [%4];"
                 : "=r"(r[0]), "=r"(r[1]), "=r"(r[2]), "=r"(r[3]) : "r"(addr));
}
__device__ __forceinline__ void ldsm_x2(uint32_t* r, uint32_t addr) {
    asm volatile("ldmatrix.sync.aligned.m8n8.x2.shared.b16 {%0,%1}, [%2];"
                 : "=r"(r[0]), "=r"(r[1]) : "r"(addr));
}

__device__ __forceinline__ void split1(float x, __nv_bfloat16& h, __nv_bfloat16& l) {
    h = __float2bfloat16(x);
    l = __float2bfloat16(x - __bfloat162float(h));
}

// ---------------------------------------------------------------------------
// bf16x3 GEMM on HMMA, length-aware tile skipping.  R7-proven mainloop.
// C[M,N] = alpha*(A @ B^T) (+ bias);  A bf16 (hi,lo) [M,*] row-stride lda,
// B bf16 (hi,lo) [N,*] row-stride ldb; K = reduction depth.
// LENMODE: 0 none; 1 proj (skip (row0%2048)>=len); 2 scores; 3 P.V
// ---------------------------------------------------------------------------
#define ROWB 80
#define SM_TILE (128 * ROWB)            // 10240
#define STAGE_BYTES (4 * SM_TILE)       // 40960: Ah, Al, Bh, Bl
#define NSTAGE 3
#define SMEM_BYTES (NSTAGE * STAGE_BYTES)  // 122880

template<bool SKIP_UPPER, bool CAUSAL_K, bool BIAS, bool OUT_SPLIT, int LENMODE>
__global__ void __launch_bounds__(256, 1)
gemm_bf16x3(const __nv_bfloat16* __restrict__ Ah, const __nv_bfloat16* __restrict__ Al,
            const __nv_bfloat16* __restrict__ Bh, const __nv_bfloat16* __restrict__ Bl,
            const float* __restrict__ bias, float* __restrict__ C,
            __nv_bfloat16* __restrict__ Ch, __nv_bfloat16* __restrict__ Cl,
            int M, int N, int K, int lda, int ldb,
            long long sA, long long sB, long long sC, float alpha)
{
    if (SKIP_UPPER && blockIdx.x > blockIdx.y) return;

    const int row0 = blockIdx.y * 128;
    const int col0 = blockIdx.x * 128;

    int Keff = K;
    if (CAUSAL_K) { const int kl = (blockIdx.y + 1) * 128; Keff = kl < K ? kl : K; }

    if (LENMODE == 1) {
        const int b = row0 >> 11;
        if ((row0 & 2047) >= g_len[b]) return;
    } else if (LENMODE == 2) {
        const int L = g_len[blockIdx.z];
        if (row0 >= L || col0 >= L) return;
    } else if (LENMODE == 3) {
        const int L = g_len[blockIdx.z];
        if (row0 >= L) return;
        const int kcap = (L + 31) & ~31;
        if (kcap < Keff) Keff = kcap;
    }
    const int nchunk = Keff >> 5;   // K-chunk = 32

    extern __shared__ char smem[];

    const int tid = threadIdx.x;
    const int wid = tid >> 5, lane = tid & 31;
    const int wr = wid >> 2;
    const int wc = wid & 3;
    const int r4 = lane >> 2;
    const int c4 = lane & 3;

    Ah += (size_t)blockIdx.z * sA;  Al += (size_t)blockIdx.z * sA;
    Bh += (size_t)blockIdx.z * sB;  Bl += (size_t)blockIdx.z * sB;

    const uint32_t sb = smem_u32(smem);

    const int aRowSel = ((lane >> 3) & 1) * 8 + (lane & 7);
    const int aColSel = (lane >> 4) * 16;
    const int bRowSel = lane & 7;
    const int bColSel = ((lane >> 3) & 1) * 16;
    const uint32_t aBase = (uint32_t)((wr * 64 + aRowSel) * ROWB + aColSel);
    const uint32_t bBase = (uint32_t)((wc * 32 + bRowSel) * ROWB + bColSel);

    auto ldstage = [&](int c, int s) {
        const long long kofs = (long long)c * 32;
        const uint32_t st = sb + s * STAGE_BYTES;
        const __nv_bfloat16* G[4] = { Ah, Al, Bh, Bl };
        #pragma unroll
        for (int t = 0; t < 4; t++) {
            const int r0 = (t < 2) ? row0 : col0;
            const int ld = (t < 2) ? lda : ldb;
            #pragma unroll
            for (int o = 0; o < 2; o++) {
                const int lin = tid + o * 256;
                const int row = lin >> 2;
                const int cb  = (lin & 3) * 16;
                const char* src = (const char*)G[t] + ((size_t)(r0 + row) * ld + kofs) * 2 + cb;
                cp_async16(st + t * SM_TILE + row * ROWB + cb, src);
            }
        }
        cp_commit();
    };

    float acc[4][4][4];
    #pragma unroll
    for (int i = 0; i < 4; i++)
        #pragma unroll
        for (int j = 0; j < 4; j++)
            #pragma unroll
            for (int r = 0; r < 4; r++) acc[i][j][r] = 0.0f;

    ldstage(0, 0);
    if (nchunk > 1) ldstage(1, 1); else cp_commit();

    for (int c = 0; c < nchunk; c++) {
        if (c + 2 < nchunk) ldstage(c + 2, (c + 2) % NSTAGE);
        else cp_commit();
        cp_wait<2>();
        __syncthreads();

        const uint32_t stg = sb + (c % NSTAGE) * STAGE_BYTES;
        #pragma unroll
        for (int ks = 0; ks < 2; ks++) {
            const uint32_t ko = ks * 32;

            uint32_t ah[4][4], al[4][4], bh[4][2], bl[4][2];
            #pragma unroll
            for (int nt = 0; nt < 4; nt++) {
                const uint32_t off = stg + bBase + nt * (8 * ROWB) + ko;
                ldsm_x2(bh[nt], off + 2 * SM_TILE);
                ldsm_x2(bl[nt], off + 3 * SM_TILE);
            }
            #pragma unroll
            for (int mt = 0; mt < 4; mt++) {
                const uint32_t off = stg + aBase + mt * (16 * ROWB) + ko;
                ldsm_x4(ah[mt], off);
                ldsm_x4(al[mt], off + SM_TILE);
            }

            #pragma unroll
            for (int mt = 0; mt < 4; mt++)
                #pragma unroll
                for (int nt = 0; nt < 4; nt++)
                    mma16816(acc[mt][nt], ah[mt], bh[nt]);
            #pragma unroll
            for (int mt = 0; mt < 4; mt++)
                #pragma unroll
                for (int nt = 0; nt < 4; nt++)
                    mma16816(acc[mt][nt], ah[mt], bl[nt]);
            #pragma unroll
            for (int mt = 0; mt < 4; mt++)
                #pragma unroll
                for (int nt = 0; nt < 4; nt++)
                    mma16816(acc[mt][nt], al[mt], bh[nt]);
        }
        __syncthreads();
    }

    // epilogue
    #pragma unroll
    for (int mt = 0; mt < 4; mt++) {
        const int r = row0 + wr * 64 + mt * 16 + r4;
        #pragma unroll
        for (int nt = 0; nt < 4; nt++) {
            const int cidx = col0 + wc * 32 + nt * 8 + c4 * 2;
            float b0 = 0.f, b1 = 0.f;
            if (BIAS) { b0 = __ldg(bias + cidx); b1 = __ldg(bias + cidx + 1); }
            const float v00 = alpha * acc[mt][nt][0] + b0;
            const float v01 = alpha * acc[mt][nt][1] + b1;
            const float v10 = alpha * acc[mt][nt][2] + b0;
            const float v11 = alpha * acc[mt][nt][3] + b1;
            if (OUT_SPLIT) {
                __nv_bfloat16 h0, l0, h1, l1;
                split1(v00, h0, l0); split1(v01, h1, l1);
                *(__nv_bfloat162*)(Ch + (size_t)r * N + cidx) = __nv_bfloat162(h0, h1);
                *(__nv_bfloat162*)(Cl + (size_t)r * N + cidx) = __nv_bfloat162(l0, l1);
                split1(v10, h0, l0); split1(v11, h1, l1);
                *(__nv_bfloat162*)(Ch + (size_t)(r + 8) * N + cidx) = __nv_bfloat162(h0, h1);
                *(__nv_bfloat162*)(Cl + (size_t)(r + 8) * N + cidx) = __nv_bfloat162(l0, l1);
            } else {
                float* Cz = C + (size_t)blockIdx.z * sC;
                *(float2*)(Cz + (size_t)r * N + cidx)       = make_float2(v00, v01);
                *(float2*)(Cz + (size_t)(r + 8) * N + cidx) = make_float2(v10, v11);
            }
        }
    }
}

// ---------------------------------------------------------------------------
__global__ void compute_len(const int* __restrict__ mask)
{
    const int b = blockIdx.x;
    const int tid = threadIdx.x;
    __shared__ int red[256];
    int s = 0;
    for (int k = tid; k < SS; k += 256) s += mask[b * SS + k];
    red[tid] = s;
    __syncthreads();
    for (int o = 128; o > 0; o >>= 1) {
        if (tid < o) red[tid] += red[tid + o];
        __syncthreads();
    }
    if (tid == 0) g_len[b] = SS - red[0];
}

// combined bias [bq | bk]
__global__ void build_bqk(const float* __restrict__ bq, const float* __restrict__ bk)
{
    const int i = threadIdx.x;
    g_bqk[i] = (i < DKK) ? bq[i] : bk[i - DKK];
}

// ---------------------------------------------------------------------------
// x column mean, two-stage.
// ---------------------------------------------------------------------------
__global__ void x_colmean_part(const float* __restrict__ x)
{
    const int d = blockIdx.x * 256 + threadIdx.x;
    const int b = blockIdx.y;
    const int sl = blockIdx.z;
    const float* xb = x + (size_t)b * SS * DD + (size_t)sl * 128 * DD + d;
    float s = 0.0f;
    #pragma unroll 8
    for (int k = 0; k < 128; k++) s += xb[(size_t)k * DD];
    g_xpart[sl][b][d] = s;
}
__global__ void x_colmean_finish()
{
    const int d = blockIdx.x * 256 + threadIdx.x;
    const int b = blockIdx.y;
    float s = 0.0f;
    #pragma unroll
    for (int sl = 0; sl < KSLICE; sl++) s += g_xpart[sl][b][d];
    g_xmean[b * DD + d] = s * (1.0f / (float)SS);
}

// ---------------------------------------------------------------------------
// vmean = xmean @ Wv + bv, two-stage (64 slices of 16 k-rows).
// ---------------------------------------------------------------------------
__global__ void vmean_part(const float* __restrict__ Wv)
{
    const int d = blockIdx.x * 256 + threadIdx.x;   // 0..1023
    const int sl = blockIdx.y;                      // 0..63
    float acc[BB] = {0.f, 0.f, 0.f, 0.f};
    #pragma unroll
    for (int kk = 0; kk < 16; kk++) {
        const int k = sl * 16 + kk;
        const float w = __ldg(Wv + (size_t)k * DD + d);
        #pragma unroll
        for (int b = 0; b < BB; b++) acc[b] += g_xmean[b * DD + k] * w;
    }
    #pragma unroll
    for (int b = 0; b < BB; b++) g_vpart[sl][b][d] = acc[b];
}
__global__ void vmean_finish(const float* __restrict__ bv)
{
    const int d = blockIdx.x * 256 + threadIdx.x;
    const int b = blockIdx.y;
    float s = __ldg(bv + d);
    #pragma unroll
    for (int sl = 0; sl < VSLICE; sl++) s += g_vpart[sl][b][d];
    g_vmean[b * DD + d] = s;
}

// ---------------------------------------------------------------------------
__global__ void split_fp32(const float* __restrict__ src,
                           __nv_bfloat16* __restrict__ hi, __nv_bfloat16* __restrict__ lo,
                           long long n4)
{
    const long long i = (long long)blockIdx.x * blockDim.x + threadIdx.x;
    if (i >= n4) return;
    float4 v = ((const float4*)src)[i];
    __nv_bfloat16 h0, h1, h2, h3, l0, l1, l2, l3;
    split1(v.x, h0, l0); split1(v.y, h1, l1); split1(v.z, h2, l2); split1(v.w, h3, l3);
    __nv_bfloat162* H = (__nv_bfloat162*)hi;
    __nv_bfloat162* L = (__nv_bfloat162*)lo;
    H[2 * i]     = __nv_bfloat162(h0, h1);
    H[2 * i + 1] = __nv_bfloat162(h2, h3);
    L[2 * i]     = __nv_bfloat162(l0, l1);
    L[2 * i + 1] = __nv_bfloat162(l2, l3);
}

// ---------------------------------------------------------------------------
__global__ void transpose_split(const float* __restrict__ in,
                                __nv_bfloat16* __restrict__ oh, __nv_bfloat16* __restrict__ ol,
                                int R, int C, long long sIn, long long sOut, int uselen)
{
    const int c0 = blockIdx.x * 32, r0 = blockIdx.y * 32;
    if (uselen && r0 >= g_len[blockIdx.z]) return;
    __shared__ float t[32][33];
    in += (size_t)blockIdx.z * sIn;
    oh += (size_t)blockIdx.z * sOut;
    ol += (size_t)blockIdx.z * sOut;
    const int tx = threadIdx.x & 31, ty = threadIdx.x >> 5;
    #pragma unroll
    for (int k = 0; k < 32; k += 8)
        t[ty + k][tx] = in[(size_t)(r0 + ty + k) * C + c0 + tx];
    __syncthreads();
    #pragma unroll
    for (int k = 0; k < 32; k += 8) {
        __nv_bfloat16 h, l;
        split1(t[tx][ty + k], h, l);
        oh[(size_t)(c0 + ty + k) * R + r0 + tx] = h;
        ol[(size_t)(c0 + ty + k) * R + r0 + tx] = l;
    }
}

// ---------------------------------------------------------------------------
__global__ void masked_softmax(const int* __restrict__ mask)
{
    const int q = blockIdx.x;
    const int b = blockIdx.y;
    if (mask[b * SS + q] != 0) return;

    const size_t off = ((size_t)b * SS + q) * SS;
    const float* row = g_s + off;
    __nv_bfloat16* ph = g_ph + off;
    __nv_bfloat16* pl = g_pl + off;
    const int tid = threadIdx.x;

    const int L   = g_len[b];
    const int cap = (L + 31) & ~31;

    __shared__ float red[256];

    float vals[8];
    float m = -INFINITY;
    #pragma unroll
    for (int it = 0; it < 8; it++) {
        const int k = tid + it * 256;
        float s = -INFINITY;
        if (k < cap) {
            const bool valid = (k <= q) && (mask[b * SS + k] == 0);
            s = valid ? row[k] : -INFINITY;
        }
        vals[it] = s;
        m = fmaxf(m, s);
    }
    red[tid] = m;
    __syncthreads();
    for (int o = 128; o > 0; o >>= 1) {
        if (tid < o) red[tid] = fmaxf(red[tid], red[tid + o]);
        __syncthreads();
    }
    m = red[0];
    __syncthreads();

    float sum = 0.0f;
    #pragma unroll
    for (int it = 0; it < 8; it++) {
        const float e = (vals[it] == -INFINITY) ? 0.0f : __expf(vals[it] - m);
        vals[it] = e;
        sum += e;
    }
    red[tid] = sum;
    __syncthreads();
    for (int o = 128; o > 0; o >>= 1) {
        if (tid < o) red[tid] += red[tid + o];
        __syncthreads();
    }
    const float inv = 1.0f / red[0];

    #pragma unroll
    for (int it = 0; it < 8; it++) {
        const int k = tid + it * 256;
        if (k < cap) {
            __nv_bfloat16 h, l;
            split1(vals[it] * inv, h, l);
            ph[k] = h;
            pl[k] = l;
        }
    }
}

// ---------------------------------------------------------------------------
__global__ void scatter_padded(const int* __restrict__ mask, float* __restrict__ out)
{
    const int q = blockIdx.x;
    const int b = blockIdx.y;
    if (mask[b * SS + q] == 0) return;
    const int tid = threadIdx.x;
    float* o = out + ((size_t)b * SS + q) * DD;
    const float* vm = g_vmean + b * DD;
    #pragma unroll
    for (int it = 0; it < 4; it++) o[tid + it * 256] = vm[tid + it * 256];
}

// ---------------------------------------------------------------------------
extern "C" void kernel_launch(void* const* d_in, const int* in_sizes, int n_in,
                              void* d_out, int out_size)
{
    const float* x    = (const float*)d_in[0];
    const int*   mask = (const int*)d_in[1];
    const float* Wq   = (const float*)d_in[2];
    const float* bq   = (const float*)d_in[3];
    const float* Wk   = (const float*)d_in[4];
    const float* bk   = (const float*)d_in[5];
    const float* Wv   = (const float*)d_in[6];
    const float* bv   = (const float*)d_in[7];
    float* out = (float*)d_out;

    cudaFuncSetAttribute(gemm_bf16x3<false, false, true, true, 1>,
                         cudaFuncAttributeMaxDynamicSharedMemorySize, SMEM_BYTES);
    cudaFuncSetAttribute(gemm_bf16x3<false, false, true, false, 1>,
                         cudaFuncAttributeMaxDynamicSharedMemorySize, SMEM_BYTES);
    cudaFuncSetAttribute(gemm_bf16x3<true, false, false, false, 2>,
                         cudaFuncAttributeMaxDynamicSharedMemorySize, SMEM_BYTES);
    cudaFuncSetAttribute(gemm_bf16x3<false, true, false, false, 3>,
                         cudaFuncAttributeMaxDynamicSharedMemorySize, SMEM_BYTES);

    __nv_bfloat16 *xh, *xl, *wqkth, *wqktl, *wvth, *wvtl;
    __nv_bfloat16 *qkh, *qkl, *vth, *vtl, *ph, *pl;
    float *v, *s, *bqk;
    cudaGetSymbolAddress((void**)&xh, g_xh);      cudaGetSymbolAddress((void**)&xl, g_xl);
    cudaGetSymbolAddress((void**)&wqkth, g_wqkt_h); cudaGetSymbolAddress((void**)&wqktl, g_wqkt_l);
    cudaGetSymbolAddress((void**)&wvth, g_wvt_h); cudaGetSymbolAddress((void**)&wvtl, g_wvt_l);
    cudaGetSymbolAddress((void**)&qkh, g_qkh);    cudaGetSymbolAddress((void**)&qkl, g_qkl);
    cudaGetSymbolAddress((void**)&v, g_v);
    cudaGetSymbolAddress((void**)&vth, g_vth);    cudaGetSymbolAddress((void**)&vtl, g_vtl);
    cudaGetSymbolAddress((void**)&s, g_s);
    cudaGetSymbolAddress((void**)&ph, g_ph);      cudaGetSymbolAddress((void**)&pl, g_pl);
    cudaGetSymbolAddress((void**)&bqk, g_bqk);

    const float scale = 1.0f / sqrtf((float)DKK);

    // 0. lengths; combined bias; xmean (2-stage); vmean (2-stage)
    compute_len<<<BB, 256>>>(mask);
    build_bqk<<<1, 2 * DKK>>>(bq, bk);
    x_colmean_part<<<dim3(DD / 256, BB, KSLICE), 256>>>(x);
    x_colmean_finish<<<dim3(DD / 256, BB), 256>>>();
    vmean_part<<<dim3(DD / 256, VSLICE), 256>>>(Wv);
    vmean_finish<<<dim3(DD / 256, BB), 256>>>(bv);

    // 1. split x into bf16 hi/lo
    {
        long long n4 = (long long)MTOT * DD / 4;
        split_fp32<<<(unsigned)((n4 + 255) / 256), 256>>>(x, xh, xl, n4);
    }
    // 2. transpose + split weights.  Wq -> rows 0..127 of WqkT, Wk -> 128..255
    transpose_split<<<dim3(DKK / 32, DD / 32, 1), 256>>>(Wq, wqkth, wqktl, DD, DKK, 0, 0, 0);
    transpose_split<<<dim3(DKK / 32, DD / 32, 1), 256>>>(Wk, wqkth + (size_t)DKK * DD,
                                                         wqktl + (size_t)DKK * DD, DD, DKK, 0, 0, 0);
    transpose_split<<<dim3(DD / 32, DD / 32, 1), 256>>>(Wv, wvth, wvtl, DD, DD, 0, 0, 0);

    // 3a. fused q|k projection: [8192, 256] = x @ [Wq|Wk], 128 CTAs
    gemm_bf16x3<false, false, true, true, 1><<<dim3(2 * DKK / 128, MTOT / 128, 1), 256, SMEM_BYTES>>>(
        xh, xl, wqkth, wqktl, bqk, nullptr, qkh, qkl,
        MTOT, 2 * DKK, DD, DD, DD, 0, 0, 0, 1.0f);
    // 3b. v projection
    gemm_bf16x3<false, false, true, false, 1><<<dim3(DD / 128, MTOT / 128, 1), 256, SMEM_BYTES>>>(
        xh, xl, wvth, wvtl, bv, v, nullptr, nullptr,
        MTOT, DD, DD, DD, DD, 0, 0, 0, 1.0f);

    // 4. transpose+split v per batch (skip rows >= len)
    transpose_split<<<dim3(DD / 32, SS / 32, BB), 256>>>(
        v, vth, vtl, SS, DD, (long long)SS * DD, (long long)SS * DD, 1);

    // 5. scores = q @ k^T from the combined buffer (A: cols 0-127, B: cols
    //    128-255, row stride 256), lower-triangle tiles clipped to len
    gemm_bf16x3<true, false, false, false, 2><<<dim3(SS / 128, SS / 128, BB), 256, SMEM_BYTES>>>(
        qkh, qkl, qkh + DKK, qkl + DKK, nullptr, s, nullptr, nullptr,
        SS, SS, DKK, 2 * DKK, 2 * DKK,
        (long long)SS * 2 * DKK, (long long)SS * 2 * DKK, (long long)SS * SS, scale);

    // 6. masked softmax -> P (bf16 hi/lo), bounded to round_up(len,32)
    masked_softmax<<<dim3(SS, BB), 256>>>(mask);

    // 7. out = P @ V^T-layout, K truncated to min(causal, len); skip rows>=len
    gemm_bf16x3<false, true, false, false, 3><<<dim3(DD / 128, SS / 128, BB), 256, SMEM_BYTES>>>(
        ph, pl, vth, vtl, nullptr, out, nullptr, nullptr,
        SS, DD, SS, SS, SS,
        (long long)SS * SS, (long long)DD * SS, (long long)SS * DD, 1.0f);

    // 8. padded rows <- uniform attention
    scatter_padded<<<dim3(SS, BB), 256>>>(mask, out);
}